// round 13
// baseline (speedup 1.0000x reference)
#include <cuda_runtime.h>
#include <cuda_fp16.h>
#include <math.h>
#include <stdint.h>

#define N_ 4
#define C_ 128
#define COUT_ 128
#define H_ 96
#define W_ 96
#define HW_ (H_*W_)
#define GN_GROUPS_ 8
#define GN_EPS_ 1e-5f
#define CNT_PER_GROUP_ (16.0f*HW_)

// dcn region: 8 rows x 16 cols of pixels (N=128), M=128, K=1152
#define TILEH_ 8
#define TILEW_ 16
#define NREG_ 72            // (96/8)*(96/16)
#define WR_ 12
#define WC_ 20
#define WWORDS_ 240         // WR_*WC_ half2 words per channel
#define SROW_ 21            // samp row stride in uint32 words (42 halves)

// k_dcn dynamic smem map (bytes)  [R9-best structure]
#define SM_BIDX  0          // 2304
#define SM_WGT   2304       // 18432 -> 20736
#define SM_RED   20736      // 256 -> 20992
#define SM_WIN2  20992      // 30720 -> 51712
#define SM_SAMP  51712      // 10752 -> 62464
#define SM_ASM   62464      // 8192 -> 70656
#define SM_TOT   70656

// k_prep dynamic smem map (bytes)
#define HP_WIN   0          // 128*120*4 = 61440  ([c][px(10,str12)][py])
#define HP_WHS   61440      // 128*9*16 = 18432 -> 79872
#define HP_RED   79872      // 256*16 = 4096 -> 83968
#define HP_TOT   83968
#define HB_      576        // head blocks (4 n * 144 tiles of 8x8)

// ---------------- scratch ----------------
__device__ float    g_dx[N_*HW_];
__device__ float    g_dy[N_*HW_];
__device__ float    g_mask[N_*HW_];
__device__ uint4    g_wA[36*512];                // A-fragment-ordered fp16 weights (294KB)
__device__ float    g_part[N_*GN_GROUPS_*NREG_*2];

// ---------------- helpers ----------------
__device__ __forceinline__ void mma16816(float* d, uint32_t a0, uint32_t a1,
                                         uint32_t a2, uint32_t a3,
                                         uint32_t b0, uint32_t b1) {
    asm volatile("mma.sync.aligned.m16n8k16.row.col.f32.f16.f16.f32 "
                 "{%0,%1,%2,%3}, {%4,%5,%6,%7}, {%8,%9}, {%0,%1,%2,%3};"
                 : "+f"(d[0]), "+f"(d[1]), "+f"(d[2]), "+f"(d[3])
                 : "r"(a0), "r"(a1), "r"(a2), "r"(a3), "r"(b0), "r"(b1));
}
__device__ __forceinline__ uint32_t packh2(float a, float b) {
    __half2 h = __floats2half2_rn(a, b);
    return *(uint32_t*)&h;
}

// ---------------- kernel 1: head conv (1 barrier) + weight prep ----------------
// blocks [0,576): head conv 8x8 tiles; blocks [576,648): A-fragment weight prep
__global__ __launch_bounds__(256) void k_prep(const float* __restrict__ x,
                                              const float* __restrict__ w_head,
                                              const float* __restrict__ b_head,
                                              const float* __restrict__ w_dcn) {
    extern __shared__ char psm[];
    int tid = threadIdx.x;
    int bx  = blockIdx.x;

    if (bx >= HB_) {
        // ---- weight prep: t indexes [ci][sub][wm][mt][lane] ----
        int t = (bx - HB_) * 256 + tid;     // 0..18431
        int lane = t & 31;
        int mt  = (t >> 5) & 3;
        int wm  = (t >> 7) & 1;
        int sub = (t >> 8) & 1;
        int ci  = t >> 9;                   // 0..35
        int cg = ci / 9, kk = ci % 9;
        int g = lane >> 2, tg = lane & 3;
        int o  = wm*64 + mt*16 + g;
        int c0 = cg*32 + sub*16 + 2*tg;
        uint4 u;
        u.x = packh2(w_dcn[o*1152 + c0*9 + kk],         w_dcn[o*1152 + (c0+1)*9 + kk]);
        u.y = packh2(w_dcn[(o+8)*1152 + c0*9 + kk],     w_dcn[(o+8)*1152 + (c0+1)*9 + kk]);
        u.z = packh2(w_dcn[o*1152 + (c0+8)*9 + kk],     w_dcn[o*1152 + (c0+9)*9 + kk]);
        u.w = packh2(w_dcn[(o+8)*1152 + (c0+8)*9 + kk], w_dcn[(o+8)*1152 + (c0+9)*9 + kk]);
        g_wA[t] = u;
        return;
    }

    // ---- head conv: one 8x8 tile, all 128 channels resident ----
    float*  winT = (float*)(psm + HP_WIN);    // [c][px(0..9) stride 12][py(0..9)]
    float4* whs  = (float4*)(psm + HP_WHS);   // [c*9+k] -> (w0,w1,w2,0)
    float4* red  = (float4*)(psm + HP_RED);   // [256]

    int n  = bx / 144;
    int t  = bx % 144;
    int ty0 = (t / 12) * 8;
    int tx0 = (t % 12) * 8;

    // load weights (broadcast-friendly float4)
    for (int i = tid; i < C_*9; i += 256) {
        int c = i / 9, k = i % 9;
        whs[i] = make_float4(w_head[(0*C_ + c)*9 + k],
                             w_head[(1*C_ + c)*9 + k],
                             w_head[(2*C_ + c)*9 + k], 0.f);
    }
    // load transposed window: 128 ch x 10x10
    for (int i = tid; i < C_*100; i += 256) {
        int c  = i / 100;
        int r  = i % 100;
        int py = r / 10, px = r % 10;
        int gy = ty0 - 1 + py, gx = tx0 - 1 + px;
        float v = 0.f;
        if (gy >= 0 && gy < H_ && gx >= 0 && gx < W_)
            v = x[((n*C_ + c)*H_ + gy)*W_ + gx];
        winT[c*120 + px*12 + py] = v;
    }
    __syncthreads();

    int cgrp = tid >> 6;          // 0..3 -> 32 channels
    int p    = tid & 63;
    int py   = p >> 3, pxx = p & 7;

    float h0 = 0.f, h1 = 0.f, h2 = 0.f;
    int cbeg = cgrp * 32;
    #pragma unroll 4
    for (int c = cbeg; c < cbeg + 32; c++) {
        const float*  wb = winT + c*120;
        const float4* wk = whs + c*9;
        #pragma unroll
        for (int ky = 0; ky < 3; ky++) {
            #pragma unroll
            for (int kx = 0; kx < 3; kx++) {
                float v = wb[(pxx + kx)*12 + (py + ky)];
                float4 wv = wk[ky*3 + kx];
                h0 += v * wv.x;
                h1 += v * wv.y;
                h2 += v * wv.z;
            }
        }
    }
    red[tid] = make_float4(h0, h1, h2, 0.f);
    __syncthreads();
    if (tid < 64) {
        float4 a = red[tid], b = red[tid+64], c4 = red[tid+128], d = red[tid+192];
        float r0 = a.x + b.x + c4.x + d.x + b_head[0];
        float r1 = a.y + b.y + c4.y + d.y + b_head[1];
        float r2 = a.z + b.z + c4.z + d.z + b_head[2];
        int gy = ty0 + (tid >> 3), gx = tx0 + (tid & 7);
        int pix = n*HW_ + gy*W_ + gx;
        g_dx[pix]   = 0.25f * tanhf(r0);
        g_dy[pix]   = 0.25f * tanhf(r1);
        g_mask[pix] = 1.f / (1.f + expf(-r2));
    }
}

// ---------------- kernel 2: deformable sampling + fp16 warp-MMA GEMM ----------------
// R9-best structure: single samp + single Asm buffers, A prefetched to regs early,
// two barriers per tap. 8 warps = 2 M-halves x 4 N-quarters.
__global__ __launch_bounds__(256, 2) void k_dcn(const float* __restrict__ x,
                                                float* __restrict__ out) {
    extern __shared__ char smem[];
    short*    bidx  = (short*)(smem + SM_BIDX);
    float4*   wgt   = (float4*)(smem + SM_WGT);
    float*    red   = (float*)(smem + SM_RED);
    __half2*  win2  = (__half2*)(smem + SM_WIN2);   // [c][r*20+x] = (v[x], v[x+1])
    uint32_t* sampW = (uint32_t*)(smem + SM_SAMP);  // [px][SROW_] words
    uint4*    AsmU  = (uint4*)(smem + SM_ASM);      // A frags, 512 uint4

    int tid = threadIdx.x, w = tid >> 5, lane = tid & 31;
    int g = lane >> 2, tg = lane & 3;
    int wm = w >> 2, ng = w & 3;
    int n0w = ng * 32;
    int bx = blockIdx.x;
    int n   = bx / NREG_;
    int reg = bx % NREG_;
    int ty0 = (reg / 6) * TILEH_;
    int tx0 = (reg % 6) * TILEW_;
    int wy0 = ty0 - 2, wx0 = tx0 - 2;

    // ---- bilinear tables: 128 px x 9 taps (mask folded) ----
    if (tid < 128) {
        int p  = tid;
        int ly = p >> 4, lx = p & 15;
        int gy = ty0 + ly, gx = tx0 + lx;
        int pix = n*HW_ + gy*W_ + gx;
        float dx = g_dx[pix], dy = g_dy[pix], m = g_mask[pix];
        const float syc[9] = {0,0,0, 1,0,-1, 1,1,-1};
        const float sxc[9] = {0,1,-1, 0,0,0, 1,-1,1};
        #pragma unroll
        for (int k = 0; k < 9; k++) {
            int ky = k / 3, kx = k % 3;
            float py = (float)(gy + ky - 1) + syc[k]*dx;
            float px = (float)(gx + kx - 1) + sxc[k]*dy;
            float fy0 = floorf(py), fx0 = floorf(px);
            int y0 = (int)fy0, x0 = (int)fx0;
            float fy = py - fy0, fx = px - fx0;
            float v00 = (y0   >= 0 && y0   < H_ && x0   >= 0 && x0   < W_) ? 1.f : 0.f;
            float v01 = (y0   >= 0 && y0   < H_ && x0+1 >= 0 && x0+1 < W_) ? 1.f : 0.f;
            float v10 = (y0+1 >= 0 && y0+1 < H_ && x0   >= 0 && x0   < W_) ? 1.f : 0.f;
            float v11 = (y0+1 >= 0 && y0+1 < H_ && x0+1 >= 0 && x0+1 < W_) ? 1.f : 0.f;
            float4 w4;
            w4.x = (1.f-fy)*(1.f-fx)*v00*m;
            w4.y = (1.f-fy)*fx      *v01*m;
            w4.z = fy      *(1.f-fx)*v10*m;
            w4.w = fy      *fx      *v11*m;
            int ly0 = min(max(y0 - wy0, 0), WR_-2);
            int lx0 = min(max(x0 - wx0, 0), WC_-2);
            bidx[k*128 + p] = (short)(ly0*WC_ + lx0);
            wgt[k*128 + p]  = w4;
        }
    }

    float acc[4][4][4];
    #pragma unroll
    for (int a = 0; a < 4; a++)
        #pragma unroll
        for (int b = 0; b < 4; b++)
            #pragma unroll
            for (int r = 0; r < 4; r++) acc[a][b][r] = 0.f;

    int sp  = tid & 127;                // sampling pixel
    int sc0 = (tid >> 7) * 16;          // sampling channel half (0 or 16)

    for (int cg = 0; cg < 4; cg++) {
        for (int i = tid; i < 32*WWORDS_; i += 256) {
            int c = i / WWORDS_;
            int rem = i % WWORDS_;
            int r = rem / WC_, xx = rem % WC_;
            int gy = wy0 + r, gx = wx0 + xx;
            float v0 = 0.f, v1 = 0.f;
            if (gy >= 0 && gy < H_) {
                const float* row = x + ((n*C_ + cg*32 + c)*H_ + gy)*W_;
                if (gx >= 0 && gx < W_)       v0 = row[gx];
                if (gx+1 >= 0 && gx+1 < W_)   v1 = row[gx+1];
            }
            win2[i] = __floats2half2_rn(v0, v1);
        }
        __syncthreads();

        for (int k = 0; k < 9; k++) {
            int ci = cg*9 + k;
            // ---- prefetch A frags into regs (overlaps sampling) ----
            const uint4* asrc = g_wA + ci*512;
            uint4 ar0 = asrc[tid];
            uint4 ar1 = asrc[tid + 256];

            // ---- sampling -> samp (fp16 pairs) ----
            {
                int base = bidx[k*128 + sp];
                float4 w4 = wgt[k*128 + sp];
                #pragma unroll
                for (int j = 0; j < 16; j += 2) {
                    int c = sc0 + j;
                    float2 c0a = __half22float2(win2[c*WWORDS_ + base]);
                    float2 c0b = __half22float2(win2[c*WWORDS_ + base + WC_]);
                    float s0 = w4.x*c0a.x + w4.y*c0a.y + w4.z*c0b.x + w4.w*c0b.y;
                    float2 c1a = __half22float2(win2[(c+1)*WWORDS_ + base]);
                    float2 c1b = __half22float2(win2[(c+1)*WWORDS_ + base + WC_]);
                    float s1 = w4.x*c1a.x + w4.y*c1a.y + w4.z*c1b.x + w4.w*c1b.y;
                    sampW[sp*SROW_ + (c >> 1)] = packh2(s0, s1);
                }
            }
            // ---- stage A frags ----
            AsmU[tid]       = ar0;
            AsmU[tid + 256] = ar1;
            __syncthreads();

            // ---- MMA phase: 2 sub-chunks of 16 channels ----
            #pragma unroll
            for (int sub = 0; sub < 2; sub++) {
                uint4 a[4];
                #pragma unroll
                for (int mt = 0; mt < 4; mt++)
                    a[mt] = AsmU[sub*256 + wm*128 + mt*32 + lane];
                uint32_t b0[4], b1[4];
                #pragma unroll
                for (int nt = 0; nt < 4; nt++) {
                    int px = n0w + nt*8 + g;
                    b0[nt] = sampW[px*SROW_ + sub*8 + tg];
                    b1[nt] = sampW[px*SROW_ + sub*8 + tg + 4];
                }
                #pragma unroll
                for (int mt = 0; mt < 4; mt++)
                    #pragma unroll
                    for (int nt = 0; nt < 4; nt++)
                        mma16816(acc[mt][nt], a[mt].x, a[mt].y, a[mt].z, a[mt].w,
                                 b0[nt], b1[nt]);
            }
            __syncthreads();
        }
    }

    // ---- epilogue: stores + GN partials ----
    float s4[4] = {0,0,0,0}, q4[4] = {0,0,0,0};
    #pragma unroll
    for (int mt = 0; mt < 4; mt++) {
        int o1 = wm*64 + mt*16 + g;
        #pragma unroll
        for (int nt = 0; nt < 4; nt++) {
            int p  = n0w + nt*8 + 2*tg;
            int gy = ty0 + (p >> 4), gx = tx0 + (p & 15);
            float2 lo = make_float2(acc[mt][nt][0], acc[mt][nt][1]);
            float2 hi = make_float2(acc[mt][nt][2], acc[mt][nt][3]);
            *(float2*)&out[((n*COUT_ + o1    )*H_ + gy)*W_ + gx] = lo;
            *(float2*)&out[((n*COUT_ + o1 + 8)*H_ + gy)*W_ + gx] = hi;
            #pragma unroll
            for (int r = 0; r < 4; r++) {
                float v = acc[mt][nt][r];
                s4[mt] += v; q4[mt] += v*v;
            }
        }
    }
    #pragma unroll
    for (int mt = 0; mt < 4; mt++) {
        #pragma unroll
        for (int o = 16; o; o >>= 1) {
            s4[mt] += __shfl_xor_sync(0xFFFFFFFFu, s4[mt], o);
            q4[mt] += __shfl_xor_sync(0xFFFFFFFFu, q4[mt], o);
        }
    }
    if (lane == 0) {
        #pragma unroll
        for (int mt = 0; mt < 4; mt++) {
            red[w*4 + mt]      = s4[mt];
            red[32 + w*4 + mt] = q4[mt];
        }
    }
    __syncthreads();
    if (tid < 8) {                    // group gid = wm*4+mt
        int gwm = tid >> 2, gmt = tid & 3;
        float s = 0.f, q = 0.f;
        #pragma unroll
        for (int j = 0; j < 4; j++) {
            s += red[(gwm*4 + j)*4 + gmt];
            q += red[32 + (gwm*4 + j)*4 + gmt];
        }
        int base = (((n*GN_GROUPS_ + tid)*NREG_) + reg)*2;
        g_part[base + 0] = s;
        g_part[base + 1] = q;
    }
}

// ---------------- kernel 3: fused GN stats + normalize + affine + relu ----------------
__global__ __launch_bounds__(256) void k_apply(float* __restrict__ out,
                                               const float* __restrict__ gamma,
                                               const float* __restrict__ beta) {
    __shared__ float sstat[4];   // meanA, rstdA, meanB, rstdB
    int tid = threadIdx.x, w = tid >> 5, lane = tid & 31;
    int bx = blockIdx.x;
    int fstart = bx * 4096;

    int cA = (fstart / HW_) % COUT_;
    int nA = fstart / (HW_*COUT_);
    int gidA = nA*GN_GROUPS_ + (cA >> 4);
    int fend = fstart + 4095;
    int cB = (fend / HW_) % COUT_;
    int nB = fend / (HW_*COUT_);
    int gidB = nB*GN_GROUPS_ + (cB >> 4);

    if (w < 2) {
        int gid = (w == 0) ? gidA : gidB;
        if (w == 0 || gidB != gidA) {
            float s = 0.f, q = 0.f;
            for (int i = lane; i < NREG_; i += 32) {
                s += g_part[(gid*NREG_ + i)*2 + 0];
                q += g_part[(gid*NREG_ + i)*2 + 1];
            }
            #pragma unroll
            for (int o = 16; o; o >>= 1) {
                s += __shfl_xor_sync(0xFFFFFFFFu, s, o);
                q += __shfl_xor_sync(0xFFFFFFFFu, q, o);
            }
            if (lane == 0) {
                float inv = 1.f / CNT_PER_GROUP_;
                float mean = s * inv;
                float var  = q * inv - mean*mean;
                sstat[w*2 + 0] = mean;
                sstat[w*2 + 1] = rsqrtf(var + GN_EPS_);
            }
        }
    }
    __syncthreads();

    #pragma unroll
    for (int u = 0; u < 4; u++) {
        int i4 = bx*1024 + u*256 + tid;
        int i = i4 * 4;
        int c = (i / HW_) % COUT_;
        int n = i / (HW_*COUT_);
        int gid = n*GN_GROUPS_ + (c >> 4);
        int sel = (gid == gidA) ? 0 : 2;
        float mean = sstat[sel + 0];
        float rstd = sstat[sel + 1];
        float sc = rstd * gamma[c];
        float sh = beta[c] - mean * sc;
        float4 v = ((float4*)out)[i4];
        v.x = fmaxf(v.x*sc + sh, 0.f);
        v.y = fmaxf(v.y*sc + sh, 0.f);
        v.z = fmaxf(v.z*sc + sh, 0.f);
        v.w = fmaxf(v.w*sc + sh, 0.f);
        ((float4*)out)[i4] = v;
    }
}

extern "C" void kernel_launch(void* const* d_in, const int* in_sizes, int n_in,
                              void* d_out, int out_size) {
    const float* x       = (const float*)d_in[0];
    const float* w_head  = (const float*)d_in[1];
    const float* b_head  = (const float*)d_in[2];
    const float* w_dcn   = (const float*)d_in[3];
    const float* gamma   = (const float*)d_in[4];
    const float* beta    = (const float*)d_in[5];
    float* out = (float*)d_out;

    cudaFuncSetAttribute(k_prep, cudaFuncAttributeMaxDynamicSharedMemorySize, HP_TOT);
    cudaFuncSetAttribute(k_dcn,  cudaFuncAttributeMaxDynamicSharedMemorySize, SM_TOT);

    k_prep<<<HB_ + 72, 256, HP_TOT>>>(x, w_head, b_head, w_dcn);
    k_dcn<<<N_*NREG_, 256, SM_TOT>>>(x, out);
    k_apply<<<N_*COUT_*HW_/4096, 256>>>(out, gamma, beta);
}

// round 16
// speedup vs baseline: 1.5447x; 1.5447x over previous
#include <cuda_runtime.h>
#include <cuda_fp16.h>
#include <math.h>
#include <stdint.h>

#define N_ 4
#define C_ 128
#define COUT_ 128
#define H_ 96
#define W_ 96
#define HW_ (H_*W_)
#define GN_GROUPS_ 8
#define GN_EPS_ 1e-5f
#define CNT_PER_GROUP_ (16.0f*HW_)

// dcn region: 8 rows x 16 cols of pixels (N=128), M=128, K=1152
#define TILEH_ 8
#define TILEW_ 16
#define NREG_ 72            // 12*6 regions per image
#define WR_ 12
#define WC_ 20
#define WWORDS_ 240         // WR_*WC_ half2 words per channel
#define SROW_ 21            // samp row stride in uint32 words

// k_dcn dynamic smem map (bytes)  [R9-best structure, unchanged]
#define SM_BIDX  0          // 2304
#define SM_WGT   2304       // 18432 -> 20736
#define SM_RED   20736      // 256 -> 20992
#define SM_WIN2  20992      // 30720 -> 51712
#define SM_SAMP  51712      // 10752 -> 62464
#define SM_ASM   62464      // 8192 -> 70656
#define SM_TOT   70656

#define HPB_ 1152           // head blocks: 4 cq * 4 n * 72 regions

// ---------------- scratch ----------------
__device__ float    g_hp[4*N_*3*HW_];            // per-quarter head partial sums
__device__ uint4    g_wA[36*512];                // A-fragment-ordered fp16 weights
__device__ float    g_part[N_*GN_GROUPS_*NREG_*2];

// ---------------- helpers ----------------
__device__ __forceinline__ void mma16816(float* d, uint32_t a0, uint32_t a1,
                                         uint32_t a2, uint32_t a3,
                                         uint32_t b0, uint32_t b1) {
    asm volatile("mma.sync.aligned.m16n8k16.row.col.f32.f16.f16.f32 "
                 "{%0,%1,%2,%3}, {%4,%5,%6,%7}, {%8,%9}, {%0,%1,%2,%3};"
                 : "+f"(d[0]), "+f"(d[1]), "+f"(d[2]), "+f"(d[3])
                 : "r"(a0), "r"(a1), "r"(a2), "r"(a3), "r"(b0), "r"(b1));
}
__device__ __forceinline__ uint32_t packh2(float a, float b) {
    __half2 h = __floats2half2_rn(a, b);
    return *(uint32_t*)&h;
}

// ---------------- kernel 1: head conv partials (fp32) + weight prep ----------------
// blocks [0,1152): head partials. block = cq*288 + n*72 + reg. 32 channels each.
// blocks [1152,1224): g_wA fragment prep.
__global__ __launch_bounds__(256) void k_prep(const float* __restrict__ x,
                                              const float* __restrict__ w_head,
                                              const float* __restrict__ w_dcn) {
    __shared__ float  win[32*180];    // 32 ch x (10 rows x 18 cols)
    __shared__ float4 whs[32*9];      // (w0,w1,w2,0) per (c_local, k)
    __shared__ float4 red[256];

    int tid = threadIdx.x;
    int bx  = blockIdx.x;

    if (bx >= HPB_) {
        // ---- g_wA prep (unchanged layout) ----
        int t = (bx - HPB_) * 256 + tid;    // 0..18431
        int lane = t & 31;
        int mt  = (t >> 5) & 3;
        int wm  = (t >> 7) & 1;
        int sub = (t >> 8) & 1;
        int ci  = t >> 9;                   // 0..35
        int cg = ci / 9, kk = ci % 9;
        int g = lane >> 2, tg = lane & 3;
        int o  = wm*64 + mt*16 + g;
        int c0 = cg*32 + sub*16 + 2*tg;
        uint4 u;
        u.x = packh2(w_dcn[o*1152 + c0*9 + kk],         w_dcn[o*1152 + (c0+1)*9 + kk]);
        u.y = packh2(w_dcn[(o+8)*1152 + c0*9 + kk],     w_dcn[(o+8)*1152 + (c0+1)*9 + kk]);
        u.z = packh2(w_dcn[o*1152 + (c0+8)*9 + kk],     w_dcn[o*1152 + (c0+9)*9 + kk]);
        u.w = packh2(w_dcn[(o+8)*1152 + (c0+8)*9 + kk], w_dcn[(o+8)*1152 + (c0+9)*9 + kk]);
        g_wA[t] = u;
        return;
    }

    // ---- head partial conv: region 8x16 px, channels [cq*32, cq*32+32) ----
    int cq  = bx / 288;
    int rb  = bx % 288;
    int n   = rb / NREG_;
    int reg = rb % NREG_;
    int ty0 = (reg / 6) * TILEH_;
    int tx0 = (reg % 6) * TILEW_;

    // weights for this quarter
    for (int i = tid; i < 32*9; i += 256) {
        int c = cq*32 + i/9;
        int k = i % 9;
        whs[i] = make_float4(w_head[(0*C_ + c)*9 + k],
                             w_head[(1*C_ + c)*9 + k],
                             w_head[(2*C_ + c)*9 + k], 0.f);
    }
    // windows: 32 ch x 10x18
    for (int i = tid; i < 32*180; i += 256) {
        int cb = i / 180;
        int r  = (i % 180) / 18, cc = (i % 180) % 18;
        int gy = ty0 - 1 + r, gx = tx0 - 1 + cc;
        float v = 0.f;
        if (gy >= 0 && gy < H_ && gx >= 0 && gx < W_)
            v = x[((n*C_ + cq*32 + cb)*H_ + gy)*W_ + gx];
        win[i] = v;
    }
    __syncthreads();

    int p  = tid & 127;
    int hf = tid >> 7;                 // 0/1 -> 16 channels each
    int ly = p >> 4, lx = p & 15;

    float h0 = 0.f, h1 = 0.f, h2 = 0.f;
    int cl0 = hf * 16;
    #pragma unroll 4
    for (int cl = cl0; cl < cl0 + 16; cl++) {
        const float*  wb = win + cl*180 + ly*18 + lx;
        const float4* wk = whs + cl*9;
        #pragma unroll
        for (int ky = 0; ky < 3; ky++) {
            #pragma unroll
            for (int kx = 0; kx < 3; kx++) {
                float v = wb[ky*18 + kx];
                float4 wv = wk[ky*3 + kx];
                h0 += v * wv.x;
                h1 += v * wv.y;
                h2 += v * wv.z;
            }
        }
    }
    red[tid] = make_float4(h0, h1, h2, 0.f);
    __syncthreads();
    if (tid < 128) {
        float4 a = red[tid], b = red[tid + 128];
        int pi = (ty0 + ly)*W_ + tx0 + lx;
        float* hp = g_hp + ((cq*N_ + n)*3)*HW_;
        hp[0*HW_ + pi] = a.x + b.x;
        hp[1*HW_ + pi] = a.y + b.y;
        hp[2*HW_ + pi] = a.z + b.z;
    }
}

// ---------------- kernel 2: deformable sampling + fp16 warp-MMA GEMM ----------------
// R9-best structure; table phase now reduces the 4 head partials + activations.
__global__ __launch_bounds__(256, 2) void k_dcn(const float* __restrict__ x,
                                                const float* __restrict__ b_head,
                                                float* __restrict__ out) {
    extern __shared__ char smem[];
    short*    bidx  = (short*)(smem + SM_BIDX);
    float4*   wgt   = (float4*)(smem + SM_WGT);
    float*    red   = (float*)(smem + SM_RED);
    __half2*  win2  = (__half2*)(smem + SM_WIN2);   // [c][r*20+x] = (v[x], v[x+1])
    uint32_t* sampW = (uint32_t*)(smem + SM_SAMP);  // [px][SROW_] words
    uint4*    AsmU  = (uint4*)(smem + SM_ASM);      // A frags, 512 uint4

    int tid = threadIdx.x, w = tid >> 5, lane = tid & 31;
    int g = lane >> 2, tg = lane & 3;
    int wm = w >> 2, ng = w & 3;
    int n0w = ng * 32;
    int bx = blockIdx.x;
    int n   = bx / NREG_;
    int reg = bx % NREG_;
    int ty0 = (reg / 6) * TILEH_;
    int tx0 = (reg % 6) * TILEW_;
    int wy0 = ty0 - 2, wx0 = tx0 - 2;

    // ---- head reduce + bilinear tables: 128 px x 9 taps (mask folded) ----
    if (tid < 128) {
        int p  = tid;
        int ly = p >> 4, lx = p & 15;
        int gy = ty0 + ly, gx = tx0 + lx;
        int pi = gy*W_ + gx;
        float h0 = b_head[0], h1 = b_head[1], h2 = b_head[2];
        #pragma unroll
        for (int q = 0; q < 4; q++) {
            const float* hp = g_hp + ((q*N_ + n)*3)*HW_;
            h0 += hp[0*HW_ + pi];
            h1 += hp[1*HW_ + pi];
            h2 += hp[2*HW_ + pi];
        }
        float dx = 0.25f * tanhf(h0);
        float dy = 0.25f * tanhf(h1);
        float m  = 1.f / (1.f + expf(-h2));

        const float syc[9] = {0,0,0, 1,0,-1, 1,1,-1};
        const float sxc[9] = {0,1,-1, 0,0,0, 1,-1,1};
        #pragma unroll
        for (int k = 0; k < 9; k++) {
            int ky = k / 3, kx = k % 3;
            float py = (float)(gy + ky - 1) + syc[k]*dx;
            float px = (float)(gx + kx - 1) + sxc[k]*dy;
            float fy0 = floorf(py), fx0 = floorf(px);
            int y0 = (int)fy0, x0 = (int)fx0;
            float fy = py - fy0, fx = px - fx0;
            float v00 = (y0   >= 0 && y0   < H_ && x0   >= 0 && x0   < W_) ? 1.f : 0.f;
            float v01 = (y0   >= 0 && y0   < H_ && x0+1 >= 0 && x0+1 < W_) ? 1.f : 0.f;
            float v10 = (y0+1 >= 0 && y0+1 < H_ && x0   >= 0 && x0   < W_) ? 1.f : 0.f;
            float v11 = (y0+1 >= 0 && y0+1 < H_ && x0+1 >= 0 && x0+1 < W_) ? 1.f : 0.f;
            float4 w4;
            w4.x = (1.f-fy)*(1.f-fx)*v00*m;
            w4.y = (1.f-fy)*fx      *v01*m;
            w4.z = fy      *(1.f-fx)*v10*m;
            w4.w = fy      *fx      *v11*m;
            int ly0 = min(max(y0 - wy0, 0), WR_-2);
            int lx0 = min(max(x0 - wx0, 0), WC_-2);
            bidx[k*128 + p] = (short)(ly0*WC_ + lx0);
            wgt[k*128 + p]  = w4;
        }
    }

    float acc[4][4][4];
    #pragma unroll
    for (int a = 0; a < 4; a++)
        #pragma unroll
        for (int b = 0; b < 4; b++)
            #pragma unroll
            for (int r = 0; r < 4; r++) acc[a][b][r] = 0.f;

    int sp  = tid & 127;                // sampling pixel
    int sc0 = (tid >> 7) * 16;          // sampling channel half (0 or 16)

    for (int cg = 0; cg < 4; cg++) {
        for (int i = tid; i < 32*WWORDS_; i += 256) {
            int c = i / WWORDS_;
            int rem = i % WWORDS_;
            int r = rem / WC_, xx = rem % WC_;
            int gy = wy0 + r, gx = wx0 + xx;
            float v0 = 0.f, v1 = 0.f;
            if (gy >= 0 && gy < H_) {
                const float* row = x + ((n*C_ + cg*32 + c)*H_ + gy)*W_;
                if (gx >= 0 && gx < W_)       v0 = row[gx];
                if (gx+1 >= 0 && gx+1 < W_)   v1 = row[gx+1];
            }
            win2[i] = __floats2half2_rn(v0, v1);
        }
        __syncthreads();

        for (int k = 0; k < 9; k++) {
            int ci = cg*9 + k;
            // ---- prefetch A frags into regs (overlaps sampling) ----
            const uint4* asrc = g_wA + ci*512;
            uint4 ar0 = asrc[tid];
            uint4 ar1 = asrc[tid + 256];

            // ---- sampling -> samp (fp16 pairs) ----
            {
                int base = bidx[k*128 + sp];
                float4 w4 = wgt[k*128 + sp];
                #pragma unroll
                for (int j = 0; j < 16; j += 2) {
                    int c = sc0 + j;
                    float2 c0a = __half22float2(win2[c*WWORDS_ + base]);
                    float2 c0b = __half22float2(win2[c*WWORDS_ + base + WC_]);
                    float s0 = w4.x*c0a.x + w4.y*c0a.y + w4.z*c0b.x + w4.w*c0b.y;
                    float2 c1a = __half22float2(win2[(c+1)*WWORDS_ + base]);
                    float2 c1b = __half22float2(win2[(c+1)*WWORDS_ + base + WC_]);
                    float s1 = w4.x*c1a.x + w4.y*c1a.y + w4.z*c1b.x + w4.w*c1b.y;
                    sampW[sp*SROW_ + (c >> 1)] = packh2(s0, s1);
                }
            }
            // ---- stage A frags ----
            AsmU[tid]       = ar0;
            AsmU[tid + 256] = ar1;
            __syncthreads();

            // ---- MMA phase: 2 sub-chunks of 16 channels ----
            #pragma unroll
            for (int sub = 0; sub < 2; sub++) {
                uint4 a[4];
                #pragma unroll
                for (int mt = 0; mt < 4; mt++)
                    a[mt] = AsmU[sub*256 + wm*128 + mt*32 + lane];
                uint32_t b0[4], b1[4];
                #pragma unroll
                for (int nt = 0; nt < 4; nt++) {
                    int px = n0w + nt*8 + g;
                    b0[nt] = sampW[px*SROW_ + sub*8 + tg];
                    b1[nt] = sampW[px*SROW_ + sub*8 + tg + 4];
                }
                #pragma unroll
                for (int mt = 0; mt < 4; mt++)
                    #pragma unroll
                    for (int nt = 0; nt < 4; nt++)
                        mma16816(acc[mt][nt], a[mt].x, a[mt].y, a[mt].z, a[mt].w,
                                 b0[nt], b1[nt]);
            }
            __syncthreads();
        }
    }

    // ---- epilogue: stores + GN partials ----
    float s4[4] = {0,0,0,0}, q4[4] = {0,0,0,0};
    #pragma unroll
    for (int mt = 0; mt < 4; mt++) {
        int o1 = wm*64 + mt*16 + g;
        #pragma unroll
        for (int nt = 0; nt < 4; nt++) {
            int p  = n0w + nt*8 + 2*tg;
            int gy = ty0 + (p >> 4), gx = tx0 + (p & 15);
            float2 lo = make_float2(acc[mt][nt][0], acc[mt][nt][1]);
            float2 hi = make_float2(acc[mt][nt][2], acc[mt][nt][3]);
            *(float2*)&out[((n*COUT_ + o1    )*H_ + gy)*W_ + gx] = lo;
            *(float2*)&out[((n*COUT_ + o1 + 8)*H_ + gy)*W_ + gx] = hi;
            #pragma unroll
            for (int r = 0; r < 4; r++) {
                float v = acc[mt][nt][r];
                s4[mt] += v; q4[mt] += v*v;
            }
        }
    }
    #pragma unroll
    for (int mt = 0; mt < 4; mt++) {
        #pragma unroll
        for (int o = 16; o; o >>= 1) {
            s4[mt] += __shfl_xor_sync(0xFFFFFFFFu, s4[mt], o);
            q4[mt] += __shfl_xor_sync(0xFFFFFFFFu, q4[mt], o);
        }
    }
    if (lane == 0) {
        #pragma unroll
        for (int mt = 0; mt < 4; mt++) {
            red[w*4 + mt]      = s4[mt];
            red[32 + w*4 + mt] = q4[mt];
        }
    }
    __syncthreads();
    if (tid < 8) {                    // group gid = wm*4+mt
        int gwm = tid >> 2, gmt = tid & 3;
        float s = 0.f, q = 0.f;
        #pragma unroll
        for (int j = 0; j < 4; j++) {
            s += red[(gwm*4 + j)*4 + gmt];
            q += red[32 + (gwm*4 + j)*4 + gmt];
        }
        int base = (((n*GN_GROUPS_ + tid)*NREG_) + reg)*2;
        g_part[base + 0] = s;
        g_part[base + 1] = q;
    }
}

// ---------------- kernel 3: fused GN stats + normalize + affine + relu ----------------
__global__ __launch_bounds__(256) void k_apply(float* __restrict__ out,
                                               const float* __restrict__ gamma,
                                               const float* __restrict__ beta) {
    __shared__ float sstat[4];   // meanA, rstdA, meanB, rstdB
    int tid = threadIdx.x, w = tid >> 5, lane = tid & 31;
    int bx = blockIdx.x;
    int fstart = bx * 4096;

    int cA = (fstart / HW_) % COUT_;
    int nA = fstart / (HW_*COUT_);
    int gidA = nA*GN_GROUPS_ + (cA >> 4);
    int fend = fstart + 4095;
    int cB = (fend / HW_) % COUT_;
    int nB = fend / (HW_*COUT_);
    int gidB = nB*GN_GROUPS_ + (cB >> 4);

    if (w < 2) {
        int gid = (w == 0) ? gidA : gidB;
        if (w == 0 || gidB != gidA) {
            float s = 0.f, q = 0.f;
            for (int i = lane; i < NREG_; i += 32) {
                s += g_part[(gid*NREG_ + i)*2 + 0];
                q += g_part[(gid*NREG_ + i)*2 + 1];
            }
            #pragma unroll
            for (int o = 16; o; o >>= 1) {
                s += __shfl_xor_sync(0xFFFFFFFFu, s, o);
                q += __shfl_xor_sync(0xFFFFFFFFu, q, o);
            }
            if (lane == 0) {
                float inv = 1.f / CNT_PER_GROUP_;
                float mean = s * inv;
                float var  = q * inv - mean*mean;
                sstat[w*2 + 0] = mean;
                sstat[w*2 + 1] = rsqrtf(var + GN_EPS_);
            }
        }
    }
    __syncthreads();

    #pragma unroll
    for (int u = 0; u < 4; u++) {
        int i4 = bx*1024 + u*256 + tid;
        int i = i4 * 4;
        int c = (i / HW_) % COUT_;
        int n = i / (HW_*COUT_);
        int gid = n*GN_GROUPS_ + (c >> 4);
        int sel = (gid == gidA) ? 0 : 2;
        float mean = sstat[sel + 0];
        float rstd = sstat[sel + 1];
        float sc = rstd * gamma[c];
        float sh = beta[c] - mean * sc;
        float4 v = ((float4*)out)[i4];
        v.x = fmaxf(v.x*sc + sh, 0.f);
        v.y = fmaxf(v.y*sc + sh, 0.f);
        v.z = fmaxf(v.z*sc + sh, 0.f);
        v.w = fmaxf(v.w*sc + sh, 0.f);
        ((float4*)out)[i4] = v;
    }
}

extern "C" void kernel_launch(void* const* d_in, const int* in_sizes, int n_in,
                              void* d_out, int out_size) {
    const float* x       = (const float*)d_in[0];
    const float* w_head  = (const float*)d_in[1];
    const float* b_head  = (const float*)d_in[2];
    const float* w_dcn   = (const float*)d_in[3];
    const float* gamma   = (const float*)d_in[4];
    const float* beta    = (const float*)d_in[5];
    float* out = (float*)d_out;

    cudaFuncSetAttribute(k_dcn, cudaFuncAttributeMaxDynamicSharedMemorySize, SM_TOT);

    k_prep<<<HPB_ + 72, 256>>>(x, w_head, w_dcn);
    k_dcn<<<N_*NREG_, 256, SM_TOT>>>(x, b_head, out);
    k_apply<<<N_*COUT_*HW_/4096, 256>>>(out, gamma, beta);
}

// round 17
// speedup vs baseline: 1.6570x; 1.0727x over previous
#include <cuda_runtime.h>
#include <cuda_fp16.h>
#include <math.h>
#include <stdint.h>

#define N_ 4
#define C_ 128
#define COUT_ 128
#define H_ 96
#define W_ 96
#define HW_ (H_*W_)
#define GN_GROUPS_ 8
#define GN_EPS_ 1e-5f
#define CNT_PER_GROUP_ (16.0f*HW_)

// dcn region: 8 rows x 16 cols of pixels (N=128), M=128, K=1152
#define TILEH_ 8
#define TILEW_ 16
#define NREG_ 72            // 12*6 regions per image
#define WR_ 12
#define WC_ 20
#define WWORDS_ 240         // WR_*WC_ half2 words per channel
#define SROW_ 21            // samp row stride in uint32 words

// k_dcn dynamic smem map (bytes)  [R9/R16-best structure, unchanged]
#define SM_BIDX  0          // 2304
#define SM_WGT   2304       // 18432 -> 20736
#define SM_RED   20736      // 256 -> 20992
#define SM_WIN2  20992      // 30720 -> 51712
#define SM_SAMP  51712      // 10752 -> 62464
#define SM_ASM   62464      // 8192 -> 70656
#define SM_TOT   70656

#define HPB_ 1152           // head blocks: 4 cq * 4 n * 72 regions
#define HWS_ 24             // head window row stride (floats) -> conflict-free

// ---------------- scratch ----------------
__device__ float    g_hp[4*N_*3*HW_];            // per-quarter head partial sums
__device__ uint4    g_wA[36*512];                // A-fragment-ordered fp16 weights
__device__ float    g_part[N_*GN_GROUPS_*NREG_*2];

// ---------------- helpers ----------------
__device__ __forceinline__ void mma16816(float* d, uint32_t a0, uint32_t a1,
                                         uint32_t a2, uint32_t a3,
                                         uint32_t b0, uint32_t b1) {
    asm volatile("mma.sync.aligned.m16n8k16.row.col.f32.f16.f16.f32 "
                 "{%0,%1,%2,%3}, {%4,%5,%6,%7}, {%8,%9}, {%0,%1,%2,%3};"
                 : "+f"(d[0]), "+f"(d[1]), "+f"(d[2]), "+f"(d[3])
                 : "r"(a0), "r"(a1), "r"(a2), "r"(a3), "r"(b0), "r"(b1));
}
__device__ __forceinline__ uint32_t packh2(float a, float b) {
    __half2 h = __floats2half2_rn(a, b);
    return *(uint32_t*)&h;
}

// ---------------- kernel 1: head conv partials (fp32) + weight prep ----------------
// blocks [0,1152): head partials. block = cq*288 + n*72 + reg. 32 channels each.
// threads: 64 vertical px-pairs x 4 groups of 8 channels.
// blocks [1152,1224): g_wA fragment prep.
__global__ __launch_bounds__(256) void k_prep(const float* __restrict__ x,
                                              const float* __restrict__ w_head,
                                              const float* __restrict__ w_dcn) {
    __shared__ float  win[32*10*HWS_];   // 32 ch x 10 rows x stride24 (cols 0..17 valid)
    __shared__ float4 whs[32*9];         // (w0,w1,w2,0) per (c_local, k)
    __shared__ float4 red[512];          // 2 per thread (px row pair)

    int tid = threadIdx.x;
    int bx  = blockIdx.x;

    if (bx >= HPB_) {
        // ---- g_wA prep (unchanged layout) ----
        int t = (bx - HPB_) * 256 + tid;    // 0..18431
        int lane = t & 31;
        int mt  = (t >> 5) & 3;
        int wm  = (t >> 7) & 1;
        int sub = (t >> 8) & 1;
        int ci  = t >> 9;                   // 0..35
        int cg = ci / 9, kk = ci % 9;
        int g = lane >> 2, tg = lane & 3;
        int o  = wm*64 + mt*16 + g;
        int c0 = cg*32 + sub*16 + 2*tg;
        uint4 u;
        u.x = packh2(w_dcn[o*1152 + c0*9 + kk],         w_dcn[o*1152 + (c0+1)*9 + kk]);
        u.y = packh2(w_dcn[(o+8)*1152 + c0*9 + kk],     w_dcn[(o+8)*1152 + (c0+1)*9 + kk]);
        u.z = packh2(w_dcn[o*1152 + (c0+8)*9 + kk],     w_dcn[o*1152 + (c0+9)*9 + kk]);
        u.w = packh2(w_dcn[(o+8)*1152 + (c0+8)*9 + kk], w_dcn[(o+8)*1152 + (c0+9)*9 + kk]);
        g_wA[t] = u;
        return;
    }

    // ---- head partial conv: region 8x16 px, channels [cq*32, cq*32+32) ----
    int cq  = bx / 288;
    int rb  = bx % 288;
    int n   = rb / NREG_;
    int reg = rb % NREG_;
    int ty0 = (reg / 6) * TILEH_;
    int tx0 = (reg % 6) * TILEW_;

    // weights for this quarter
    for (int i = tid; i < 32*9; i += 256) {
        int c = cq*32 + i/9;
        int k = i % 9;
        whs[i] = make_float4(w_head[(0*C_ + c)*9 + k],
                             w_head[(1*C_ + c)*9 + k],
                             w_head[(2*C_ + c)*9 + k], 0.f);
    }
    // windows: 32 ch x 10x18 (stride 24)
    bool interior = (ty0 > 0) && (ty0 + TILEH_ < H_) && (tx0 > 0) && (tx0 + TILEW_ < W_);
    const float* xq = x + (n*C_ + cq*32)*HW_;
    if (interior) {
        for (int i = tid; i < 32*180; i += 256) {
            int cb  = i / 180;
            int rem = i - cb*180;
            int r   = rem / 18, cc = rem - r*18;
            win[cb*240 + r*HWS_ + cc] =
                xq[cb*HW_ + (ty0 - 1 + r)*W_ + (tx0 - 1 + cc)];
        }
    } else {
        for (int i = tid; i < 32*180; i += 256) {
            int cb  = i / 180;
            int rem = i - cb*180;
            int r   = rem / 18, cc = rem - r*18;
            int gy = ty0 - 1 + r, gx = tx0 - 1 + cc;
            float v = 0.f;
            if (gy >= 0 && gy < H_ && gx >= 0 && gx < W_)
                v = xq[cb*HW_ + gy*W_ + gx];
            win[cb*240 + r*HWS_ + cc] = v;
        }
    }
    __syncthreads();

    int vp  = tid & 63;               // vertical pixel pair
    int cq8 = tid >> 6;               // 8-channel group
    int r0  = (vp >> 4) * 2;          // px rows r0, r0+1
    int lx  = vp & 15;

    float h0a=0.f,h1a=0.f,h2a=0.f,h0b=0.f,h1b=0.f,h2b=0.f;
    #pragma unroll 2
    for (int j = 0; j < 8; j++) {
        int cl = cq8*8 + j;
        const float*  wb = win + cl*240 + r0*HWS_ + lx;
        const float4* wk = whs + cl*9;
        float v[4][3];
        #pragma unroll
        for (int rr = 0; rr < 4; rr++)
            #pragma unroll
            for (int cc = 0; cc < 3; cc++)
                v[rr][cc] = wb[rr*HWS_ + cc];
        #pragma unroll
        for (int ky = 0; ky < 3; ky++)
            #pragma unroll
            for (int kx = 0; kx < 3; kx++) {
                float4 wv = wk[ky*3 + kx];
                float a = v[ky][kx], b = v[ky+1][kx];
                h0a += a*wv.x; h1a += a*wv.y; h2a += a*wv.z;
                h0b += b*wv.x; h1b += b*wv.y; h2b += b*wv.z;
            }
    }
    red[tid*2 + 0] = make_float4(h0a, h1a, h2a, 0.f);
    red[tid*2 + 1] = make_float4(h0b, h1b, h2b, 0.f);
    __syncthreads();
    if (tid < 128) {
        int pr = tid >> 4, pc = tid & 15;
        int vp2 = (pr >> 1)*16 + pc, slot = pr & 1;
        float s0 = 0.f, s1 = 0.f, s2 = 0.f;
        #pragma unroll
        for (int q = 0; q < 4; q++) {
            float4 t = red[(q*64 + vp2)*2 + slot];
            s0 += t.x; s1 += t.y; s2 += t.z;
        }
        int pi = (ty0 + pr)*W_ + tx0 + pc;
        float* hp = g_hp + ((cq*N_ + n)*3)*HW_;
        hp[0*HW_ + pi] = s0;
        hp[1*HW_ + pi] = s1;
        hp[2*HW_ + pi] = s2;
    }
}

// ---------------- kernel 2: deformable sampling + fp16 warp-MMA GEMM ----------------
// R16 verbatim: table phase reduces the 4 head partials + activations.
__global__ __launch_bounds__(256, 2) void k_dcn(const float* __restrict__ x,
                                                const float* __restrict__ b_head,
                                                float* __restrict__ out) {
    extern __shared__ char smem[];
    short*    bidx  = (short*)(smem + SM_BIDX);
    float4*   wgt   = (float4*)(smem + SM_WGT);
    float*    red   = (float*)(smem + SM_RED);
    __half2*  win2  = (__half2*)(smem + SM_WIN2);   // [c][r*20+x] = (v[x], v[x+1])
    uint32_t* sampW = (uint32_t*)(smem + SM_SAMP);  // [px][SROW_] words
    uint4*    AsmU  = (uint4*)(smem + SM_ASM);      // A frags, 512 uint4

    int tid = threadIdx.x, w = tid >> 5, lane = tid & 31;
    int g = lane >> 2, tg = lane & 3;
    int wm = w >> 2, ng = w & 3;
    int n0w = ng * 32;
    int bx = blockIdx.x;
    int n   = bx / NREG_;
    int reg = bx % NREG_;
    int ty0 = (reg / 6) * TILEH_;
    int tx0 = (reg % 6) * TILEW_;
    int wy0 = ty0 - 2, wx0 = tx0 - 2;

    // ---- head reduce + bilinear tables: 128 px x 9 taps (mask folded) ----
    if (tid < 128) {
        int p  = tid;
        int ly = p >> 4, lx = p & 15;
        int gy = ty0 + ly, gx = tx0 + lx;
        int pi = gy*W_ + gx;
        float h0 = b_head[0], h1 = b_head[1], h2 = b_head[2];
        #pragma unroll
        for (int q = 0; q < 4; q++) {
            const float* hp = g_hp + ((q*N_ + n)*3)*HW_;
            h0 += hp[0*HW_ + pi];
            h1 += hp[1*HW_ + pi];
            h2 += hp[2*HW_ + pi];
        }
        float dx = 0.25f * tanhf(h0);
        float dy = 0.25f * tanhf(h1);
        float m  = 1.f / (1.f + expf(-h2));

        const float syc[9] = {0,0,0, 1,0,-1, 1,1,-1};
        const float sxc[9] = {0,1,-1, 0,0,0, 1,-1,1};
        #pragma unroll
        for (int k = 0; k < 9; k++) {
            int ky = k / 3, kx = k % 3;
            float py = (float)(gy + ky - 1) + syc[k]*dx;
            float px = (float)(gx + kx - 1) + sxc[k]*dy;
            float fy0 = floorf(py), fx0 = floorf(px);
            int y0 = (int)fy0, x0 = (int)fx0;
            float fy = py - fy0, fx = px - fx0;
            float v00 = (y0   >= 0 && y0   < H_ && x0   >= 0 && x0   < W_) ? 1.f : 0.f;
            float v01 = (y0   >= 0 && y0   < H_ && x0+1 >= 0 && x0+1 < W_) ? 1.f : 0.f;
            float v10 = (y0+1 >= 0 && y0+1 < H_ && x0   >= 0 && x0   < W_) ? 1.f : 0.f;
            float v11 = (y0+1 >= 0 && y0+1 < H_ && x0+1 >= 0 && x0+1 < W_) ? 1.f : 0.f;
            float4 w4;
            w4.x = (1.f-fy)*(1.f-fx)*v00*m;
            w4.y = (1.f-fy)*fx      *v01*m;
            w4.z = fy      *(1.f-fx)*v10*m;
            w4.w = fy      *fx      *v11*m;
            int ly0 = min(max(y0 - wy0, 0), WR_-2);
            int lx0 = min(max(x0 - wx0, 0), WC_-2);
            bidx[k*128 + p] = (short)(ly0*WC_ + lx0);
            wgt[k*128 + p]  = w4;
        }
    }

    float acc[4][4][4];
    #pragma unroll
    for (int a = 0; a < 4; a++)
        #pragma unroll
        for (int b = 0; b < 4; b++)
            #pragma unroll
            for (int r = 0; r < 4; r++) acc[a][b][r] = 0.f;

    int sp  = tid & 127;                // sampling pixel
    int sc0 = (tid >> 7) * 16;          // sampling channel half (0 or 16)

    for (int cg = 0; cg < 4; cg++) {
        for (int i = tid; i < 32*WWORDS_; i += 256) {
            int c = i / WWORDS_;
            int rem = i % WWORDS_;
            int r = rem / WC_, xx = rem % WC_;
            int gy = wy0 + r, gx = wx0 + xx;
            float v0 = 0.f, v1 = 0.f;
            if (gy >= 0 && gy < H_) {
                const float* row = x + ((n*C_ + cg*32 + c)*H_ + gy)*W_;
                if (gx >= 0 && gx < W_)       v0 = row[gx];
                if (gx+1 >= 0 && gx+1 < W_)   v1 = row[gx+1];
            }
            win2[i] = __floats2half2_rn(v0, v1);
        }
        __syncthreads();

        for (int k = 0; k < 9; k++) {
            int ci = cg*9 + k;
            // ---- prefetch A frags into regs (overlaps sampling) ----
            const uint4* asrc = g_wA + ci*512;
            uint4 ar0 = asrc[tid];
            uint4 ar1 = asrc[tid + 256];

            // ---- sampling -> samp (fp16 pairs) ----
            {
                int base = bidx[k*128 + sp];
                float4 w4 = wgt[k*128 + sp];
                #pragma unroll
                for (int j = 0; j < 16; j += 2) {
                    int c = sc0 + j;
                    float2 c0a = __half22float2(win2[c*WWORDS_ + base]);
                    float2 c0b = __half22float2(win2[c*WWORDS_ + base + WC_]);
                    float s0 = w4.x*c0a.x + w4.y*c0a.y + w4.z*c0b.x + w4.w*c0b.y;
                    float2 c1a = __half22float2(win2[(c+1)*WWORDS_ + base]);
                    float2 c1b = __half22float2(win2[(c+1)*WWORDS_ + base + WC_]);
                    float s1 = w4.x*c1a.x + w4.y*c1a.y + w4.z*c1b.x + w4.w*c1b.y;
                    sampW[sp*SROW_ + (c >> 1)] = packh2(s0, s1);
                }
            }
            // ---- stage A frags ----
            AsmU[tid]       = ar0;
            AsmU[tid + 256] = ar1;
            __syncthreads();

            // ---- MMA phase: 2 sub-chunks of 16 channels ----
            #pragma unroll
            for (int sub = 0; sub < 2; sub++) {
                uint4 a[4];
                #pragma unroll
                for (int mt = 0; mt < 4; mt++)
                    a[mt] = AsmU[sub*256 + wm*128 + mt*32 + lane];
                uint32_t b0[4], b1[4];
                #pragma unroll
                for (int nt = 0; nt < 4; nt++) {
                    int px = n0w + nt*8 + g;
                    b0[nt] = sampW[px*SROW_ + sub*8 + tg];
                    b1[nt] = sampW[px*SROW_ + sub*8 + tg + 4];
                }
                #pragma unroll
                for (int mt = 0; mt < 4; mt++)
                    #pragma unroll
                    for (int nt = 0; nt < 4; nt++)
                        mma16816(acc[mt][nt], a[mt].x, a[mt].y, a[mt].z, a[mt].w,
                                 b0[nt], b1[nt]);
            }
            __syncthreads();
        }
    }

    // ---- epilogue: stores + GN partials ----
    float s4[4] = {0,0,0,0}, q4[4] = {0,0,0,0};
    #pragma unroll
    for (int mt = 0; mt < 4; mt++) {
        int o1 = wm*64 + mt*16 + g;
        #pragma unroll
        for (int nt = 0; nt < 4; nt++) {
            int p  = n0w + nt*8 + 2*tg;
            int gy = ty0 + (p >> 4), gx = tx0 + (p & 15);
            float2 lo = make_float2(acc[mt][nt][0], acc[mt][nt][1]);
            float2 hi = make_float2(acc[mt][nt][2], acc[mt][nt][3]);
            *(float2*)&out[((n*COUT_ + o1    )*H_ + gy)*W_ + gx] = lo;
            *(float2*)&out[((n*COUT_ + o1 + 8)*H_ + gy)*W_ + gx] = hi;
            #pragma unroll
            for (int r = 0; r < 4; r++) {
                float v = acc[mt][nt][r];
                s4[mt] += v; q4[mt] += v*v;
            }
        }
    }
    #pragma unroll
    for (int mt = 0; mt < 4; mt++) {
        #pragma unroll
        for (int o = 16; o; o >>= 1) {
            s4[mt] += __shfl_xor_sync(0xFFFFFFFFu, s4[mt], o);
            q4[mt] += __shfl_xor_sync(0xFFFFFFFFu, q4[mt], o);
        }
    }
    if (lane == 0) {
        #pragma unroll
        for (int mt = 0; mt < 4; mt++) {
            red[w*4 + mt]      = s4[mt];
            red[32 + w*4 + mt] = q4[mt];
        }
    }
    __syncthreads();
    if (tid < 8) {                    // group gid = wm*4+mt
        int gwm = tid >> 2, gmt = tid & 3;
        float s = 0.f, q = 0.f;
        #pragma unroll
        for (int j = 0; j < 4; j++) {
            s += red[(gwm*4 + j)*4 + gmt];
            q += red[32 + (gwm*4 + j)*4 + gmt];
        }
        int base = (((n*GN_GROUPS_ + tid)*NREG_) + reg)*2;
        g_part[base + 0] = s;
        g_part[base + 1] = q;
    }
}

// ---------------- kernel 3: fused GN stats + normalize + affine + relu ----------------
__global__ __launch_bounds__(256) void k_apply(float* __restrict__ out,
                                               const float* __restrict__ gamma,
                                               const float* __restrict__ beta) {
    __shared__ float sstat[4];   // meanA, rstdA, meanB, rstdB
    int tid = threadIdx.x, w = tid >> 5, lane = tid & 31;
    int bx = blockIdx.x;
    int fstart = bx * 4096;

    int cA = (fstart / HW_) % COUT_;
    int nA = fstart / (HW_*COUT_);
    int gidA = nA*GN_GROUPS_ + (cA >> 4);
    int fend = fstart + 4095;
    int cB = (fend / HW_) % COUT_;
    int nB = fend / (HW_*COUT_);
    int gidB = nB*GN_GROUPS_ + (cB >> 4);

    if (w < 2) {
        int gid = (w == 0) ? gidA : gidB;
        if (w == 0 || gidB != gidA) {
            float s = 0.f, q = 0.f;
            for (int i = lane; i < NREG_; i += 32) {
                s += g_part[(gid*NREG_ + i)*2 + 0];
                q += g_part[(gid*NREG_ + i)*2 + 1];
            }
            #pragma unroll
            for (int o = 16; o; o >>= 1) {
                s += __shfl_xor_sync(0xFFFFFFFFu, s, o);
                q += __shfl_xor_sync(0xFFFFFFFFu, q, o);
            }
            if (lane == 0) {
                float inv = 1.f / CNT_PER_GROUP_;
                float mean = s * inv;
                float var  = q * inv - mean*mean;
                sstat[w*2 + 0] = mean;
                sstat[w*2 + 1] = rsqrtf(var + GN_EPS_);
            }
        }
    }
    __syncthreads();

    #pragma unroll
    for (int u = 0; u < 4; u++) {
        int i4 = bx*1024 + u*256 + tid;
        int i = i4 * 4;
        int c = (i / HW_) % COUT_;
        int n = i / (HW_*COUT_);
        int gid = n*GN_GROUPS_ + (c >> 4);
        int sel = (gid == gidA) ? 0 : 2;
        float mean = sstat[sel + 0];
        float rstd = sstat[sel + 1];
        float sc = rstd * gamma[c];
        float sh = beta[c] - mean * sc;
        float4 v = ((float4*)out)[i4];
        v.x = fmaxf(v.x*sc + sh, 0.f);
        v.y = fmaxf(v.y*sc + sh, 0.f);
        v.z = fmaxf(v.z*sc + sh, 0.f);
        v.w = fmaxf(v.w*sc + sh, 0.f);
        ((float4*)out)[i4] = v;
    }
}

extern "C" void kernel_launch(void* const* d_in, const int* in_sizes, int n_in,
                              void* d_out, int out_size) {
    const float* x       = (const float*)d_in[0];
    const float* w_head  = (const float*)d_in[1];
    const float* b_head  = (const float*)d_in[2];
    const float* w_dcn   = (const float*)d_in[3];
    const float* gamma   = (const float*)d_in[4];
    const float* beta    = (const float*)d_in[5];
    float* out = (float*)d_out;

    cudaFuncSetAttribute(k_dcn, cudaFuncAttributeMaxDynamicSharedMemorySize, SM_TOT);

    k_prep<<<HPB_ + 72, 256>>>(x, w_head, w_dcn);
    k_dcn<<<N_*NREG_, 256, SM_TOT>>>(x, b_head, out);
    k_apply<<<N_*COUT_*HW_/4096, 256>>>(out, gamma, beta);
}